// round 1
// baseline (speedup 1.0000x reference)
#include <cuda_runtime.h>
#include <cstdint>
#include <cstddef>

#define NUM_LAYERS 6

// ---------------------------------------------------------------------------
// Shapes:
//   x: (4,256,64,64) f32      y: (4,512) f32
//   ch_conv_w: (256,256)      ch_conv_b: (256)
//   affine_w: (6,256,512)     affine_b: (6,256)     mod_w: (6,256,256)
//   out: (4,256,128,128) f32
//
// Exact algebraic reductions (see analysis):
//   * 2x2 spatial upsample commutes with all layers -> compute on 64x64 only
//   * channel repeat folded into conv weights (WU = Wc[j/2]+Wc[128+j/2], WB)
//   * wmod row-normalization is a closed-form per-row scalar alpha[b,o]
// State recurrence per conv pixel: u0=WU*x, b0=WB*x;
//   6x { h = WL[l,b]*u ; b += gelu(h) ; u += b } ; out = 0.5*u replicated 2x2.
// ---------------------------------------------------------------------------

__device__ float g_alpha[NUM_LAYERS * 4 * 256];
__device__ float g_WLt[NUM_LAYERS * 4 * 256 * 256];  // [l][b][k][o] = wmod[b,o,k]
__device__ float g_WUt[256 * 256];                   // [k][j]
__device__ float g_WBt[256 * 256];                   // [k][j]
__device__ float g_ub[256];
__device__ float g_bb[256];

// ---- prep: per-row modulation scalar alpha[b,o] ---------------------------
__global__ void prep_alpha(const float* __restrict__ affine_w,
                           const float* __restrict__ affine_b,
                           const float* __restrict__ mod_w,
                           const float* __restrict__ y) {
    int lay = blockIdx.x, b = blockIdx.y, o = threadIdx.x;
    const float* aw = affine_w + ((size_t)(lay * 256 + o)) * 512;
    const float* yv = y + b * 512;
    float s = affine_b[lay * 256 + o];
    for (int t = 0; t < 512; t++) s += aw[t] * yv[t];
    const float* mw = mod_w + ((size_t)(lay * 256 + o)) * 256;
    float q = 0.f;
    for (int k = 0; k < 256; k++) { float m = mw[k]; q += m * m; }
    float sp = s + 1.f;
    g_alpha[(lay * 4 + b) * 256 + o] = sp * rsqrtf(sp * sp * q + 1e-8f);
}

// ---- prep: scaled + transposed layer weights WLt[l][b][k][o] --------------
__global__ void prep_wl(const float* __restrict__ mod_w) {
    int lb = blockIdx.x;            // lay*4 + b
    int lay = lb >> 2;
    int o0 = blockIdx.y * 32, k0 = blockIdx.z * 32;
    int tx = threadIdx.x, ty = threadIdx.y;
    __shared__ float tile[32][33];
#pragma unroll
    for (int r = 0; r < 4; r++) {
        int oo = ty + r * 8;
        int o = o0 + oo;
        tile[oo][tx] = mod_w[((size_t)(lay * 256 + o)) * 256 + k0 + tx] *
                       g_alpha[lb * 256 + o];
    }
    __syncthreads();
    float* dst = g_WLt + ((size_t)lb << 16);
#pragma unroll
    for (int r = 0; r < 4; r++) {
        int kk = ty + r * 8;
        dst[(size_t)(k0 + kk) * 256 + o0 + tx] = tile[tx][kk];
    }
}

// ---- prep: folded conv weights (transposed) + biases ----------------------
__global__ void prep_wuwb(const float* __restrict__ cw, const float* __restrict__ cb) {
    int j = blockIdx.x;
    int k = threadIdx.x;
    int jh = j >> 1;
    float a = cw[jh * 256 + k];
    float c = cw[(128 + jh) * 256 + k];
    g_WUt[k * 256 + j] = a + c;
    g_WBt[k * 256 + j] = c;
    if (k == 0) {
        g_ub[j] = cb[jh] + cb[128 + jh];
        g_bb[j] = cb[128 + jh];
    }
}

// ---- packed f32x2 helpers (full-rate fp32 path on sm_103a) ----------------
__device__ __forceinline__ unsigned long long dup2(float a) {
    unsigned long long r;
    unsigned int ai = __float_as_uint(a);
    asm("mov.b64 %0, {%1, %1};" : "=l"(r) : "r"(ai));
    return r;
}
__device__ __forceinline__ void ffma2(unsigned long long& d, unsigned long long a,
                                      unsigned long long b) {
    asm("fma.rn.f32x2 %0, %1, %2, %0;" : "+l"(d) : "l"(a), "l"(b));
}
__device__ __forceinline__ float2 unp(unsigned long long v) {
    unsigned int lo, hi;
    asm("mov.b64 {%0, %1}, %2;" : "=r"(lo), "=r"(hi) : "l"(v));
    return make_float2(__uint_as_float(lo), __uint_as_float(hi));
}
__device__ __forceinline__ float gelu_exact(float x) {
    return 0.5f * x * (1.f + erff(x * 0.70710678118654752440f));
}

// ---- core 256x32 GEMM over K=256: acc[o 4][p-pair 4] ----------------------
// Wg: global [k][o] (pre-transposed, pre-scaled).  src: SMEM [256][36].
__device__ __forceinline__ void gemm256(const float* __restrict__ Wg,
                                        const float* __restrict__ src,
                                        float* __restrict__ w_s,
                                        int o_base, int p_base, int t,
                                        unsigned long long acc[4][4]) {
#pragma unroll 1
    for (int kc = 0; kc < 8; kc++) {
        __syncthreads();
#pragma unroll
        for (int r = 0; r < 8; r++) {
            int j = r * 256 + t;
            int k = j >> 6, o4 = (j & 63) << 2;
            float4 v = *(const float4*)(Wg + (((size_t)(kc * 32 + k)) << 8) + o4);
            *(float4*)(w_s + k * 264 + o4) = v;
        }
        __syncthreads();
        const float* srck = src + kc * 32 * 36;
#pragma unroll 8
        for (int k = 0; k < 32; k++) {
            float4 wv = *(const float4*)(w_s + k * 264 + o_base);
            unsigned long long w0 = dup2(wv.x), w1 = dup2(wv.y);
            unsigned long long w2 = dup2(wv.z), w3 = dup2(wv.w);
            const float* ur = srck + k * 36 + p_base;
            ulonglong2 ua = *(const ulonglong2*)ur;
            ulonglong2 ub = *(const ulonglong2*)(ur + 4);
            ffma2(acc[0][0], w0, ua.x); ffma2(acc[0][1], w0, ua.y);
            ffma2(acc[0][2], w0, ub.x); ffma2(acc[0][3], w0, ub.y);
            ffma2(acc[1][0], w1, ua.x); ffma2(acc[1][1], w1, ua.y);
            ffma2(acc[1][2], w1, ub.x); ffma2(acc[1][3], w1, ub.y);
            ffma2(acc[2][0], w2, ua.x); ffma2(acc[2][1], w2, ua.y);
            ffma2(acc[2][2], w2, ub.x); ffma2(acc[2][3], w2, ub.y);
            ffma2(acc[3][0], w3, ua.x); ffma2(acc[3][1], w3, ua.y);
            ffma2(acc[3][2], w3, ub.x); ffma2(acc[3][3], w3, ub.y);
        }
    }
    __syncthreads();
}

// ---- fused main kernel ----------------------------------------------------
// grid (128 tiles, 4 batches), 256 threads. Tile = 32 conv pixels (half a row).
// SMEM: u[256][36] | b[256][36] | w[32][264]  = 107,520 B
__global__ __launch_bounds__(256, 2)
void fused_main(const float* __restrict__ x, float* __restrict__ out) {
    extern __shared__ float sm[];
    float* u_s = sm;            // 9216 floats
    float* b_s = sm + 9216;     // 9216 floats
    float* w_s = sm + 18432;    // 8448 floats
    int t = threadIdx.x;
    int tile = blockIdx.x;      // 0..127
    int b = blockIdx.y;         // 0..3
    int o_base = (t & 63) << 2;
    int p_base = (t >> 6) << 3;
    int q0 = tile << 5;         // conv-pixel linear offset

    // stage input tile x[b][:, q0..q0+31] into b_s (temp use as GEMM src)
    {
        const float* xb = x + ((size_t)b << 20) + q0;
        int c0 = t >> 5, p = t & 31;
#pragma unroll
        for (int it = 0; it < 32; it++) {
            int c = c0 + (it << 3);
            b_s[c * 36 + p] = xb[((size_t)c << 12) + p];
        }
    }

    unsigned long long acc[4][4];

    // GEMM 0: u0 = WU * x + ub
#pragma unroll
    for (int oi = 0; oi < 4; oi++) {
        unsigned long long bi = dup2(g_ub[o_base + oi]);
#pragma unroll
        for (int pp = 0; pp < 4; pp++) acc[oi][pp] = bi;
    }
    gemm256(g_WUt, b_s, w_s, o_base, p_base, t, acc);
#pragma unroll
    for (int oi = 0; oi < 4; oi++)
#pragma unroll
        for (int pp = 0; pp < 4; pp++)
            *(float2*)(u_s + (o_base + oi) * 36 + p_base + pp * 2) = unp(acc[oi][pp]);

    // GEMM 1: b0 = WB * x + bb   (overwrites b_s after full accumulation+sync)
#pragma unroll
    for (int oi = 0; oi < 4; oi++) {
        unsigned long long bi = dup2(g_bb[o_base + oi]);
#pragma unroll
        for (int pp = 0; pp < 4; pp++) acc[oi][pp] = bi;
    }
    gemm256(g_WBt, b_s, w_s, o_base, p_base, t, acc);
#pragma unroll
    for (int oi = 0; oi < 4; oi++)
#pragma unroll
        for (int pp = 0; pp < 4; pp++)
            *(float2*)(b_s + (o_base + oi) * 36 + p_base + pp * 2) = unp(acc[oi][pp]);

    // 6 layers: h = WL*u ; b += gelu(h) ; u += b
    for (int l = 0; l < NUM_LAYERS; l++) {
#pragma unroll
        for (int oi = 0; oi < 4; oi++)
#pragma unroll
            for (int pp = 0; pp < 4; pp++) acc[oi][pp] = 0ull;
        const float* Wl = g_WLt + ((size_t)(l * 4 + b) << 16);
        gemm256(Wl, u_s, w_s, o_base, p_base, t, acc);
#pragma unroll
        for (int oi = 0; oi < 4; oi++) {
#pragma unroll
            for (int pp = 0; pp < 4; pp++) {
                float2 h = unp(acc[oi][pp]);
                float* bp = b_s + (o_base + oi) * 36 + p_base + pp * 2;
                float* up = u_s + (o_base + oi) * 36 + p_base + pp * 2;
                float bn0 = bp[0] + gelu_exact(h.x);
                float bn1 = bp[1] + gelu_exact(h.y);
                bp[0] = bn0; bp[1] = bn1;
                up[0] += bn0; up[1] += bn1;
            }
        }
    }
    __syncthreads();

    // output: 0.5*u replicated 2x2, coalesced float2 stores
    {
        int qh = tile >> 1, qw0 = (tile & 1) << 5;
        float* ob = out + ((size_t)b << 22);
        int c0 = t >> 5, p = t & 31;
        int col = (qw0 + p) << 1;
        int row = qh << 1;
#pragma unroll
        for (int it = 0; it < 32; it++) {
            int c = c0 + (it << 3);
            float v = 0.5f * u_s[c * 36 + p];
            float2 vv = make_float2(v, v);
            float* pr = ob + (((size_t)c << 14) + ((size_t)row << 7) + col);
            *(float2*)pr = vv;
            *(float2*)(pr + 128) = vv;
        }
    }
}

// ---------------------------------------------------------------------------
extern "C" void kernel_launch(void* const* d_in, const int* in_sizes, int n_in,
                              void* d_out, int out_size) {
    const float* x  = (const float*)d_in[0];
    const float* y  = (const float*)d_in[1];
    const float* cw = (const float*)d_in[2];
    const float* cb = (const float*)d_in[3];
    const float* aw = (const float*)d_in[4];
    const float* ab = (const float*)d_in[5];
    const float* mw = (const float*)d_in[6];
    float* out = (float*)d_out;

    prep_alpha<<<dim3(NUM_LAYERS, 4), 256>>>(aw, ab, mw, y);
    prep_wl<<<dim3(NUM_LAYERS * 4, 8, 8), dim3(32, 8)>>>(mw);
    prep_wuwb<<<256, 256>>>(cw, cb);

    cudaFuncSetAttribute(fused_main, cudaFuncAttributeMaxDynamicSharedMemorySize,
                         107520);
    fused_main<<<dim3(128, 4), 256, 107520>>>(x, out);
}

// round 2
// speedup vs baseline: 1.3636x; 1.3636x over previous
#include <cuda_runtime.h>
#include <cstdint>
#include <cstddef>

#define NUM_LAYERS 6

// ---------------------------------------------------------------------------
// Shapes:
//   x: (4,256,64,64) f32      y: (4,512) f32
//   ch_conv_w: (256,256)      ch_conv_b: (256)
//   affine_w: (6,256,512)     affine_b: (6,256)     mod_w: (6,256,256)
//   out: (4,256,128,128) f32
//
// Exact algebraic reductions:
//   * 2x2 spatial upsample commutes with all layers -> compute on 64x64 only
//   * channel repeat folded into conv weights (WU = Wc[j/2]+Wc[128+j/2], WB)
//   * wmod row-normalization is a closed-form per-row scalar alpha[b,o]
// State recurrence per conv pixel: u0=WU*x, b0=WB*x;
//   6x { h = WL[l,b]*u ; b += gelu(h) ; u += b } ; out = 0.5*u replicated 2x2.
//
// R2: cp.async double-buffered weight streaming (chunk=16 k-rows) to hide
// global latency inside the barrier-fenced GEMM loop; parallel prep_alpha.
// ---------------------------------------------------------------------------

__device__ float g_alpha[NUM_LAYERS * 4 * 256];
__device__ float g_WLt[NUM_LAYERS * 4 * 256 * 256];  // [l][b][k][o] = wmod[b,o,k]
__device__ float g_WUt[256 * 256];                   // [k][j]
__device__ float g_WBt[256 * 256];                   // [k][j]
__device__ float g_ub[256];
__device__ float g_bb[256];

// ---- prep: per-row modulation scalar alpha[b,o], parallel reduction -------
__global__ void prep_alpha(const float* __restrict__ affine_w,
                           const float* __restrict__ affine_b,
                           const float* __restrict__ mod_w,
                           const float* __restrict__ y) {
    int o = blockIdx.x;        // 0..255
    int lay = blockIdx.y;      // 0..5
    int t = threadIdx.x;       // 0..127
    const float* awr = affine_w + ((size_t)(lay * 256 + o)) * 512;
    float s0 = 0.f, s1 = 0.f, s2 = 0.f, s3 = 0.f, q = 0.f;
#pragma unroll
    for (int i = t; i < 512; i += 128) {
        float a = awr[i];
        s0 += a * y[i];
        s1 += a * y[512 + i];
        s2 += a * y[1024 + i];
        s3 += a * y[1536 + i];
    }
    const float* mwr = mod_w + ((size_t)(lay * 256 + o)) * 256;
#pragma unroll
    for (int i = t; i < 256; i += 128) { float m = mwr[i]; q += m * m; }
#pragma unroll
    for (int d = 16; d >= 1; d >>= 1) {
        s0 += __shfl_xor_sync(0xffffffffu, s0, d);
        s1 += __shfl_xor_sync(0xffffffffu, s1, d);
        s2 += __shfl_xor_sync(0xffffffffu, s2, d);
        s3 += __shfl_xor_sync(0xffffffffu, s3, d);
        q  += __shfl_xor_sync(0xffffffffu, q, d);
    }
    __shared__ float red[4][5];
    int w = t >> 5;
    if ((t & 31) == 0) {
        red[w][0] = s0; red[w][1] = s1; red[w][2] = s2; red[w][3] = s3; red[w][4] = q;
    }
    __syncthreads();
    if (t == 0) {
        float S[4], Q = 0.f;
        S[0] = S[1] = S[2] = S[3] = 0.f;
#pragma unroll
        for (int i = 0; i < 4; i++) {
            S[0] += red[i][0]; S[1] += red[i][1];
            S[2] += red[i][2]; S[3] += red[i][3]; Q += red[i][4];
        }
        float bias = affine_b[lay * 256 + o];
#pragma unroll
        for (int b = 0; b < 4; b++) {
            float sp = S[b] + bias + 1.f;
            g_alpha[(lay * 4 + b) * 256 + o] = sp * rsqrtf(sp * sp * Q + 1e-8f);
        }
    }
}

// ---- prep: scaled + transposed layer weights WLt[l][b][k][o] --------------
__global__ void prep_wl(const float* __restrict__ mod_w) {
    int lb = blockIdx.x;            // lay*4 + b
    int lay = lb >> 2;
    int o0 = blockIdx.y * 32, k0 = blockIdx.z * 32;
    int tx = threadIdx.x, ty = threadIdx.y;
    __shared__ float tile[32][33];
#pragma unroll
    for (int r = 0; r < 4; r++) {
        int oo = ty + r * 8;
        int o = o0 + oo;
        tile[oo][tx] = mod_w[((size_t)(lay * 256 + o)) * 256 + k0 + tx] *
                       g_alpha[lb * 256 + o];
    }
    __syncthreads();
    float* dst = g_WLt + ((size_t)lb << 16);
#pragma unroll
    for (int r = 0; r < 4; r++) {
        int kk = ty + r * 8;
        dst[(size_t)(k0 + kk) * 256 + o0 + tx] = tile[tx][kk];
    }
}

// ---- prep: folded conv weights (transposed) + biases ----------------------
__global__ void prep_wuwb(const float* __restrict__ cw, const float* __restrict__ cb) {
    int j = blockIdx.x;
    int k = threadIdx.x;
    int jh = j >> 1;
    float a = cw[jh * 256 + k];
    float c = cw[(128 + jh) * 256 + k];
    g_WUt[k * 256 + j] = a + c;
    g_WBt[k * 256 + j] = c;
    if (k == 0) {
        g_ub[j] = cb[jh] + cb[128 + jh];
        g_bb[j] = cb[128 + jh];
    }
}

// ---- packed f32x2 helpers (full-rate fp32 path on sm_103a) ----------------
__device__ __forceinline__ unsigned long long dup2(float a) {
    unsigned long long r;
    unsigned int ai = __float_as_uint(a);
    asm("mov.b64 %0, {%1, %1};" : "=l"(r) : "r"(ai));
    return r;
}
__device__ __forceinline__ void ffma2(unsigned long long& d, unsigned long long a,
                                      unsigned long long b) {
    asm("fma.rn.f32x2 %0, %1, %2, %0;" : "+l"(d) : "l"(a), "l"(b));
}
__device__ __forceinline__ float2 unp(unsigned long long v) {
    unsigned int lo, hi;
    asm("mov.b64 {%0, %1}, %2;" : "=r"(lo), "=r"(hi) : "l"(v));
    return make_float2(__uint_as_float(lo), __uint_as_float(hi));
}
__device__ __forceinline__ float gelu_exact(float x) {
    return 0.5f * x * (1.f + erff(x * 0.70710678118654752440f));
}

// ---- cp.async helpers -----------------------------------------------------
__device__ __forceinline__ void cp16(float* dst_s, const float* src_g) {
    unsigned sd = (unsigned)__cvta_generic_to_shared(dst_s);
    asm volatile("cp.async.cg.shared.global [%0], [%1], 16;\n" :: "r"(sd), "l"(src_g));
}
__device__ __forceinline__ void cp_commit() {
    asm volatile("cp.async.commit_group;\n");
}

// issue async copy of weight chunk kc (16 k-rows of 256 floats) into wbuf
__device__ __forceinline__ void load_chunk(const float* __restrict__ Wg,
                                           float* __restrict__ wbuf,
                                           int kc, int t) {
    const float* src = Wg + (((size_t)kc * 16) << 8);
#pragma unroll
    for (int r = 0; r < 4; r++) {
        int j = r * 256 + t;
        int k = j >> 6, o4 = (j & 63) << 2;
        cp16(wbuf + k * 264 + o4, src + (k << 8) + o4);
    }
    cp_commit();
}

// ---- core 256x32 GEMM over K=256, double-buffered cp.async weights --------
// Wg: global [k][o] (pre-transposed, pre-scaled).  src: SMEM [256][36].
// w2: SMEM 2 x [16][264] chunk buffers.
__device__ __forceinline__ void gemm256(const float* __restrict__ Wg,
                                        const float* __restrict__ src,
                                        float* __restrict__ w2,
                                        int o_base, int p_base, int t,
                                        unsigned long long acc[4][4]) {
    load_chunk(Wg, w2, 0, t);
    load_chunk(Wg, w2 + 16 * 264, 1, t);
#pragma unroll 1
    for (int kc = 0; kc < 16; kc++) {
        if (kc == 15) asm volatile("cp.async.wait_group 0;\n");
        else          asm volatile("cp.async.wait_group 1;\n");
        __syncthreads();
        const float* w_s = w2 + (kc & 1) * (16 * 264);
        const float* srck = src + kc * 16 * 36;
#pragma unroll
        for (int k = 0; k < 16; k++) {
            float4 wv = *(const float4*)(w_s + k * 264 + o_base);
            unsigned long long w0 = dup2(wv.x), w1 = dup2(wv.y);
            unsigned long long w2r = dup2(wv.z), w3 = dup2(wv.w);
            const float* ur = srck + k * 36 + p_base;
            ulonglong2 ua = *(const ulonglong2*)ur;
            ulonglong2 ub = *(const ulonglong2*)(ur + 4);
            ffma2(acc[0][0], w0, ua.x); ffma2(acc[0][1], w0, ua.y);
            ffma2(acc[0][2], w0, ub.x); ffma2(acc[0][3], w0, ub.y);
            ffma2(acc[1][0], w1, ua.x); ffma2(acc[1][1], w1, ua.y);
            ffma2(acc[1][2], w1, ub.x); ffma2(acc[1][3], w1, ub.y);
            ffma2(acc[2][0], w2r, ua.x); ffma2(acc[2][1], w2r, ua.y);
            ffma2(acc[2][2], w2r, ub.x); ffma2(acc[2][3], w2r, ub.y);
            ffma2(acc[3][0], w3, ua.x); ffma2(acc[3][1], w3, ua.y);
            ffma2(acc[3][2], w3, ub.x); ffma2(acc[3][3], w3, ub.y);
        }
        __syncthreads();
        if (kc < 14) load_chunk(Wg, w2 + (kc & 1) * (16 * 264), kc + 2, t);
    }
}

// ---- fused main kernel ----------------------------------------------------
// grid (128 tiles, 4 batches), 256 threads. Tile = 32 conv pixels (half a row).
// SMEM: u[256][36] | b[256][36] | w2[2][16][264]  = 107,520 B -> 2 CTAs/SM
__global__ __launch_bounds__(256, 2)
void fused_main(const float* __restrict__ x, float* __restrict__ out) {
    extern __shared__ float sm[];
    float* u_s = sm;            // 9216 floats
    float* b_s = sm + 9216;     // 9216 floats
    float* w2 = sm + 18432;     // 8448 floats (2 x 16 x 264)
    int t = threadIdx.x;
    int tile = blockIdx.x;      // 0..127
    int b = blockIdx.y;         // 0..3
    int o_base = (t & 63) << 2;
    int p_base = (t >> 6) << 3;
    int q0 = tile << 5;         // conv-pixel linear offset

    // stage input tile x[b][:, q0..q0+31] into b_s (temp use as GEMM src)
    {
        const float* xb = x + ((size_t)b << 20) + q0;
        int c0 = t >> 5, p = t & 31;
#pragma unroll
        for (int it = 0; it < 32; it++) {
            int c = c0 + (it << 3);
            b_s[c * 36 + p] = xb[((size_t)c << 12) + p];
        }
    }

    unsigned long long acc[4][4];

    // GEMM 0: u0 = WU * x + ub
#pragma unroll
    for (int oi = 0; oi < 4; oi++) {
        unsigned long long bi = dup2(g_ub[o_base + oi]);
#pragma unroll
        for (int pp = 0; pp < 4; pp++) acc[oi][pp] = bi;
    }
    gemm256(g_WUt, b_s, w2, o_base, p_base, t, acc);
#pragma unroll
    for (int oi = 0; oi < 4; oi++)
#pragma unroll
        for (int pp = 0; pp < 4; pp++)
            *(float2*)(u_s + (o_base + oi) * 36 + p_base + pp * 2) = unp(acc[oi][pp]);

    // GEMM 1: b0 = WB * x + bb   (overwrites b_s after full accumulation+sync)
#pragma unroll
    for (int oi = 0; oi < 4; oi++) {
        unsigned long long bi = dup2(g_bb[o_base + oi]);
#pragma unroll
        for (int pp = 0; pp < 4; pp++) acc[oi][pp] = bi;
    }
    gemm256(g_WBt, b_s, w2, o_base, p_base, t, acc);
    // safe to overwrite b_s: all accumulation done; each thread writes its own slots,
    // and the next GEMM's reads are fenced by its kc=0 barrier.
    __syncthreads();
#pragma unroll
    for (int oi = 0; oi < 4; oi++)
#pragma unroll
        for (int pp = 0; pp < 4; pp++)
            *(float2*)(b_s + (o_base + oi) * 36 + p_base + pp * 2) = unp(acc[oi][pp]);

    // 6 layers: h = WL*u ; b += gelu(h) ; u += b
    for (int l = 0; l < NUM_LAYERS; l++) {
#pragma unroll
        for (int oi = 0; oi < 4; oi++)
#pragma unroll
            for (int pp = 0; pp < 4; pp++) acc[oi][pp] = 0ull;
        const float* Wl = g_WLt + ((size_t)(l * 4 + b) << 16);
        gemm256(Wl, u_s, w2, o_base, p_base, t, acc);
#pragma unroll
        for (int oi = 0; oi < 4; oi++) {
#pragma unroll
            for (int pp = 0; pp < 4; pp++) {
                float2 h = unp(acc[oi][pp]);
                float* bp = b_s + (o_base + oi) * 36 + p_base + pp * 2;
                float* up = u_s + (o_base + oi) * 36 + p_base + pp * 2;
                float bn0 = bp[0] + gelu_exact(h.x);
                float bn1 = bp[1] + gelu_exact(h.y);
                bp[0] = bn0; bp[1] = bn1;
                up[0] += bn0; up[1] += bn1;
            }
        }
    }
    __syncthreads();

    // output: 0.5*u replicated 2x2, coalesced float2 stores
    {
        int qh = tile >> 1, qw0 = (tile & 1) << 5;
        float* ob = out + ((size_t)b << 22);
        int c0 = t >> 5, p = t & 31;
        int col = (qw0 + p) << 1;
        int row = qh << 1;
#pragma unroll
        for (int it = 0; it < 32; it++) {
            int c = c0 + (it << 3);
            float v = 0.5f * u_s[c * 36 + p];
            float2 vv = make_float2(v, v);
            float* pr = ob + (((size_t)c << 14) + ((size_t)row << 7) + col);
            *(float2*)pr = vv;
            *(float2*)(pr + 128) = vv;
        }
    }
}

// ---------------------------------------------------------------------------
extern "C" void kernel_launch(void* const* d_in, const int* in_sizes, int n_in,
                              void* d_out, int out_size) {
    const float* x  = (const float*)d_in[0];
    const float* y  = (const float*)d_in[1];
    const float* cw = (const float*)d_in[2];
    const float* cb = (const float*)d_in[3];
    const float* aw = (const float*)d_in[4];
    const float* ab = (const float*)d_in[5];
    const float* mw = (const float*)d_in[6];
    float* out = (float*)d_out;

    prep_alpha<<<dim3(256, NUM_LAYERS), 128>>>(aw, ab, mw, y);
    prep_wl<<<dim3(NUM_LAYERS * 4, 8, 8), dim3(32, 8)>>>(mw);
    prep_wuwb<<<256, 256>>>(cw, cb);

    cudaFuncSetAttribute(fused_main, cudaFuncAttributeMaxDynamicSharedMemorySize,
                         107520);
    fused_main<<<dim3(128, 4), 256, 107520>>>(x, out);
}